// round 1
// baseline (speedup 1.0000x reference)
#include <cuda_runtime.h>
#include <math.h>

#define BATCH 64
#define TLEN  4096
#define BT    (BATCH*TLEN)
#define C     192

// Scratch (device globals: allocation-free per harness rules)
__device__ float g_h[(size_t)BT*C];     // 201 MB
__device__ float g_y[(size_t)BT*C];     // 201 MB
__device__ float g_p[(size_t)BT*32];    // 32 MB (29 proj outputs, padded)
__device__ float g_lad[BT];             // 1 MB

__device__ __forceinline__ void ffma2(float2 &d, const float2 &a, const float2 &b) {
    asm("fma.rn.f32x2 %0, %1, %2, %0;"
        : "+l"(*reinterpret_cast<unsigned long long*>(&d))
        : "l"(*reinterpret_cast<const unsigned long long*>(&a)),
          "l"(*reinterpret_cast<const unsigned long long*>(&b)));
}

__device__ __forceinline__ float geluf(float u) {
    return 0.5f*u*(1.f + erff(u*0.7071067811865475f));
}

// ---------------------------------------------------------------------------
// h[bt, c] = pre_w[c] * x0[b,t] + pre_b[c]
// ---------------------------------------------------------------------------
__global__ void init_h_kernel(const float* __restrict__ x,
                              const float* __restrict__ pw,
                              const float* __restrict__ pb) {
    unsigned idx = blockIdx.x*256u + threadIdx.x;
    unsigned pos = idx / 192u;
    unsigned c   = idx - pos*192u;
    unsigned b   = pos >> 12, t = pos & 4095u;
    float x0 = x[(size_t)b*2u*TLEN + t];
    g_h[idx] = fmaf(pw[c], x0, pb[c]);
}

// ---------------------------------------------------------------------------
// y = gelu(LN1(depthwise_dilated_conv(h * mask)))   one warp per position
// ---------------------------------------------------------------------------
__global__ __launch_bounds__(256) void dw_ln_gelu_kernel(
    const float* __restrict__ sw, const float* __restrict__ sb,
    const float* __restrict__ g1, const float* __restrict__ b1,
    const float* __restrict__ mask, int d)
{
    int warp = threadIdx.x >> 5, lane = threadIdx.x & 31;
    int pos = blockIdx.x*8 + warp;
    int t = pos & 4095;
    float mC = mask[pos];
    bool hasL = (t >= d), hasR = (t + d < TLEN);
    float mL = hasL ? mask[pos-d] : 0.f;
    float mR = hasR ? mask[pos+d] : 0.f;
    const float* hrow = g_h + (size_t)pos*C;
    float v[6]; float s1 = 0.f;
    #pragma unroll
    for (int k=0;k<6;k++) {
        int c = lane + 32*k;
        float y = sb[c];
        y = fmaf(sw[c*3+1], hrow[c]*mC, y);
        if (hasL) y = fmaf(sw[c*3+0], hrow[c - d*C]*mL, y);
        if (hasR) y = fmaf(sw[c*3+2], hrow[c + d*C]*mR, y);
        v[k] = y; s1 += y;
    }
    #pragma unroll
    for (int o=16;o;o>>=1) s1 += __shfl_xor_sync(0xffffffffu, s1, o);
    float mean = s1*(1.f/192.f);
    float s2 = 0.f;
    #pragma unroll
    for (int k=0;k<6;k++){ float e = v[k]-mean; s2 += e*e; }
    #pragma unroll
    for (int o=16;o;o>>=1) s2 += __shfl_xor_sync(0xffffffffu, s2, o);
    float inv = rsqrtf(s2*(1.f/192.f) + 1e-5f);
    float* yo = g_y + (size_t)pos*C;
    #pragma unroll
    for (int k=0;k<6;k++){
        int c = lane + 32*k;
        float u = fmaf(g1[c], (v[k]-mean)*inv, b1[c]);
        yo[c] = geluf(u);
    }
}

// ---------------------------------------------------------------------------
// h += gelu(LN2(W(192x192) @ y + bias))
// Block: 128 thr (4 warps), M_TILE=32 rows, warp owns 8 full rows (LN warp-local)
// K chunked by 32 through smem; packed f32x2 FMA (even/odd ci in lo/hi halves)
// ---------------------------------------------------------------------------
__global__ __launch_bounds__(128, 3) void pw_ln_gelu_res_kernel(
    const float* __restrict__ W, const float* __restrict__ bias,
    const float* __restrict__ g2, const float* __restrict__ b2)
{
    __shared__ float Ws[192*33];   // [co][ci], stride 33 -> conflict-free scalar loads
    __shared__ float ys[32*34];    // [m][ci], stride 34 -> aligned float2, broadcast reads
    int tid = threadIdx.x;
    int lane = tid & 31, w = tid >> 5;
    size_t m0 = (size_t)blockIdx.x * 32;

    float2 acc[8][6];
    #pragma unroll
    for (int r=0;r<8;r++)
        #pragma unroll
        for (int j=0;j<6;j++) acc[r][j] = make_float2(0.f,0.f);

    for (int kb = 0; kb < 192; kb += 32) {
        for (int idx = tid; idx < 192*32; idx += 128) {
            int co = idx >> 5, ci = idx & 31;
            Ws[co*33+ci] = W[co*192 + kb + ci];
        }
        for (int idx = tid; idx < 32*32; idx += 128) {
            int m = idx >> 5, ci = idx & 31;
            ys[m*34+ci] = g_y[(m0+m)*192 + kb + ci];
        }
        __syncthreads();
        #pragma unroll
        for (int ci = 0; ci < 32; ci += 2) {
            float2 bv[6];
            #pragma unroll
            for (int j=0;j<6;j++){
                int co = lane + 32*j;
                bv[j].x = Ws[co*33+ci];
                bv[j].y = Ws[co*33+ci+1];
            }
            #pragma unroll
            for (int r=0;r<8;r++){
                float2 a = *reinterpret_cast<const float2*>(&ys[(w*8+r)*34 + ci]);
                #pragma unroll
                for (int j=0;j<6;j++) ffma2(acc[r][j], a, bv[j]);
            }
        }
        __syncthreads();
    }

    #pragma unroll
    for (int r=0;r<8;r++){
        float vv[6]; float s1 = 0.f;
        #pragma unroll
        for (int j=0;j<6;j++){
            int co = lane+32*j;
            float vx = acc[r][j].x + acc[r][j].y + bias[co];
            vv[j] = vx; s1 += vx;
        }
        #pragma unroll
        for (int o=16;o;o>>=1) s1 += __shfl_xor_sync(0xffffffffu, s1, o);
        float mean = s1*(1.f/192.f);
        float s2 = 0.f;
        #pragma unroll
        for (int j=0;j<6;j++){ float e = vv[j]-mean; s2 += e*e; }
        #pragma unroll
        for (int o=16;o;o>>=1) s2 += __shfl_xor_sync(0xffffffffu, s2, o);
        float inv = rsqrtf(s2*(1.f/192.f) + 1e-5f);
        size_t rowo = (m0 + (size_t)(w*8+r))*C;
        #pragma unroll
        for (int j=0;j<6;j++){
            int co = lane+32*j;
            float u = fmaf(g2[co], (vv[j]-mean)*inv, b2[co]);
            g_h[rowo+co] += geluf(u);
        }
    }
}

// ---------------------------------------------------------------------------
// p[pos, j] = (mask * sum_ci Wp[j,ci]*h[pos,ci] + bp[j]) * mask, j<29
// one warp per position, 29 accumulators per lane, butterfly reduce
// ---------------------------------------------------------------------------
__global__ __launch_bounds__(256) void proj_kernel(
    const float* __restrict__ Wp, const float* __restrict__ bp,
    const float* __restrict__ mask)
{
    int warp = threadIdx.x >> 5, lane = threadIdx.x & 31;
    int pos = blockIdx.x*8 + warp;
    float m = mask[pos];
    const float* hrow = g_h + (size_t)pos*C;
    float hv[6];
    #pragma unroll
    for (int k=0;k<6;k++) hv[k] = hrow[lane+32*k];
    float acc[29];
    #pragma unroll
    for (int j=0;j<29;j++) acc[j]=0.f;
    #pragma unroll
    for (int k=0;k<6;k++){
        int c = lane+32*k;
        #pragma unroll
        for (int j=0;j<29;j++)
            acc[j] = fmaf(Wp[j*192+c], hv[k], acc[j]);
    }
    #pragma unroll
    for (int o=16;o;o>>=1){
        #pragma unroll
        for (int j=0;j<29;j++) acc[j] += __shfl_xor_sync(0xffffffffu, acc[j], o);
    }
    float sel = 0.f;
    #pragma unroll
    for (int j=0;j<29;j++) if (lane==j) sel = acc[j];
    if (lane < 29)
        g_p[(size_t)pos*32 + lane] = fmaf(m, sel, bp[lane]) * m;
}

// ---------------------------------------------------------------------------
// rational-quadratic spline, writes both output halves + per-position lad
// ---------------------------------------------------------------------------
__global__ __launch_bounds__(256) void spline_kernel(
    const float* __restrict__ x, const float* __restrict__ mask,
    float* __restrict__ out)
{
    int pos = blockIdx.x*256 + threadIdx.x;
    int b = pos >> 12, t = pos & 4095;
    float m = mask[pos];
    const float* p = g_p + (size_t)pos*32;
    const float SCALE = 13.856406460551018f; // sqrt(192)

    float x0v = x[(size_t)b*2*TLEN + t];
    float x1v = x[(size_t)b*2*TLEN + TLEN + t];

    float cw[11], wd[10];
    {
        float u[10]; float mx = -1e30f;
        #pragma unroll
        for (int k=0;k<10;k++){ u[k] = p[k]/SCALE; mx = fmaxf(mx,u[k]); }
        float s=0.f; float e[10];
        #pragma unroll
        for (int k=0;k<10;k++){ e[k]=expf(u[k]-mx); s+=e[k]; }
        float run=0.f; cw[0]=-5.f;
        #pragma unroll
        for (int k=0;k<10;k++){ run += 0.001f + 0.99f*(e[k]/s); cw[k+1] = 10.f*run - 5.f; }
        cw[10] = 5.f;
        #pragma unroll
        for (int k=0;k<10;k++) wd[k] = cw[k+1]-cw[k];
    }
    float ch[11], hg[10];
    {
        float u[10]; float mx = -1e30f;
        #pragma unroll
        for (int k=0;k<10;k++){ u[k] = p[10+k]/SCALE; mx = fmaxf(mx,u[k]); }
        float s=0.f; float e[10];
        #pragma unroll
        for (int k=0;k<10;k++){ e[k]=expf(u[k]-mx); s+=e[k]; }
        float run=0.f; ch[0]=-5.f;
        #pragma unroll
        for (int k=0;k<10;k++){ run += 0.001f + 0.99f*(e[k]/s); ch[k+1] = 10.f*run - 5.f; }
        ch[10] = 5.f;
        #pragma unroll
        for (int k=0;k<10;k++) hg[k] = ch[k+1]-ch[k];
    }
    float dv[11];
    dv[0] = 1.0f; dv[10] = 1.0f;   // 0.001 + softplus(log(exp(0.999)-1)) = 1.0
    #pragma unroll
    for (int k=0;k<9;k++){
        float q = p[20+k];
        float sp = (q > 20.f) ? q : log1pf(expf(q));
        dv[k+1] = 0.001f + sp;
    }
    float xin = fminf(fmaxf(x1v, -5.f), 5.f);
    int cnt = 0;
    #pragma unroll
    for (int k=0;k<10;k++) cnt += (xin >= cw[k]) ? 1 : 0;
    int bin = cnt-1; if (bin < 0) bin = 0; if (bin > 9) bin = 9;

    float icw=cw[bin], iw=wd[bin], ich=ch[bin], ih=hg[bin];
    float dl=dv[bin], dr=dv[bin+1];
    float delta = ih/iw;
    float th  = (xin - icw)/iw;
    float t1m = th*(1.f-th);
    float num = ih*(delta*th*th + dl*t1m);
    float den = delta + (dl+dr-2.f*delta)*t1m;
    float yv  = ich + num/den;
    float onem = 1.f-th;
    float dnum = delta*delta*(dr*th*th + 2.f*delta*t1m + dl*onem*onem);
    float lad  = logf(dnum) - 2.f*logf(den);
    bool inside = (x1v >= -5.f) && (x1v <= 5.f);
    float xo   = inside ? yv  : x1v;
    float ladv = inside ? lad : 0.f;

    out[(size_t)b*2*TLEN + t]        = x0v * m;
    out[(size_t)b*2*TLEN + TLEN + t] = xo  * m;
    g_lad[pos] = ladv * m;
}

// ---------------------------------------------------------------------------
// deterministic per-batch logdet reduction (fixed order, no atomics)
// ---------------------------------------------------------------------------
__global__ void logdet_kernel(float* __restrict__ out) {
    int b = blockIdx.x, tid = threadIdx.x;
    float s = 0.f;
    #pragma unroll
    for (int k=0;k<16;k++) s += g_lad[b*TLEN + k*256 + tid];
    __shared__ float sm[256];
    sm[tid] = s; __syncthreads();
    #pragma unroll
    for (int o=128;o;o>>=1){ if (tid<o) sm[tid]+=sm[tid+o]; __syncthreads(); }
    if (tid==0) out[b] = sm[0];
}

extern "C" void kernel_launch(void* const* d_in, const int* in_sizes, int n_in,
                              void* d_out, int out_size) {
    const float* x      = (const float*)d_in[0];
    const float* mask   = (const float*)d_in[1];
    const float* pre_w  = (const float*)d_in[2];
    const float* pre_b  = (const float*)d_in[3];
    const float* sep_w  = (const float*)d_in[4];
    const float* sep_b  = (const float*)d_in[5];
    const float* pw_w   = (const float*)d_in[6];
    const float* pw_b   = (const float*)d_in[7];
    const float* ln1_g  = (const float*)d_in[8];
    const float* ln1_b  = (const float*)d_in[9];
    const float* ln2_g  = (const float*)d_in[10];
    const float* ln2_b  = (const float*)d_in[11];
    const float* proj_w = (const float*)d_in[12];
    const float* proj_b = (const float*)d_in[13];
    float* out = (float*)d_out;

    init_h_kernel<<<(BT/256)*192, 256>>>(x, pre_w, pre_b);

    int d = 1;
    for (int i = 0; i < 3; i++) {
        dw_ln_gelu_kernel<<<BT/8, 256>>>(sep_w + (size_t)i*C*3, sep_b + (size_t)i*C,
                                         ln1_g + (size_t)i*C, ln1_b + (size_t)i*C,
                                         mask, d);
        pw_ln_gelu_res_kernel<<<BT/32, 128>>>(pw_w + (size_t)i*C*C, pw_b + (size_t)i*C,
                                              ln2_g + (size_t)i*C, ln2_b + (size_t)i*C);
        d *= 3;
    }

    proj_kernel<<<BT/8, 256>>>(proj_w, proj_b, mask);
    spline_kernel<<<BT/256, 256>>>(x, mask, out);
    logdet_kernel<<<64, 256>>>(out + (size_t)BATCH*2*TLEN);
}

// round 2
// speedup vs baseline: 1.3746x; 1.3746x over previous
#include <cuda_runtime.h>
#include <math.h>

#define BATCH 64
#define TLEN  4096
#define BT    (BATCH*TLEN)
#define C     192

// Scratch (device globals: allocation-free per harness rules)
__device__ float g_h[(size_t)BT*C];     // 201 MB
__device__ float g_y[(size_t)BT*C];     // 201 MB
__device__ float g_p[(size_t)BT*32];    // 32 MB (29 proj outputs, padded)
__device__ float g_lad[BT];             // 1 MB

__device__ __forceinline__ float geluf(float u) {
    return 0.5f*u*(1.f + erff(u*0.7071067811865475f));
}

// ---------------------------------------------------------------------------
// y = gelu(LN1(depthwise_dilated_conv(h * mask)))   one warp per position
// first=1: h is computed inline as pre_w[c]*x0 + pre_b[c]  (layer 0)
// ---------------------------------------------------------------------------
__global__ __launch_bounds__(256) void dw_ln_gelu_kernel(
    const float* __restrict__ sw, const float* __restrict__ sb,
    const float* __restrict__ g1, const float* __restrict__ b1,
    const float* __restrict__ mask, int d,
    const float* __restrict__ x,  const float* __restrict__ prew,
    const float* __restrict__ preb, int first)
{
    int warp = threadIdx.x >> 5, lane = threadIdx.x & 31;
    int pos = blockIdx.x*8 + warp;
    int t = pos & 4095;
    float mC = mask[pos];
    bool hasL = (t >= d), hasR = (t + d < TLEN);
    float mL = hasL ? mask[pos-d] : 0.f;
    float mR = hasR ? mask[pos+d] : 0.f;

    float x0C=0.f, x0L=0.f, x0R=0.f;
    const float* hrow = g_h + (size_t)pos*C;
    if (first) {
        int b = pos >> 12;
        const float* xr = x + (size_t)b*2*TLEN;
        x0C = xr[t];
        if (hasL) x0L = xr[t-d];
        if (hasR) x0R = xr[t+d];
    }

    float v[6]; float s1 = 0.f;
    #pragma unroll
    for (int k=0;k<6;k++) {
        int c = lane + 32*k;
        float hC, hL = 0.f, hR = 0.f;
        if (first) {
            float pw = prew[c], pb = preb[c];
            hC = fmaf(pw, x0C, pb);
            if (hasL) hL = fmaf(pw, x0L, pb);
            if (hasR) hR = fmaf(pw, x0R, pb);
        } else {
            hC = hrow[c];
            if (hasL) hL = hrow[c - d*C];
            if (hasR) hR = hrow[c + d*C];
        }
        float y = sb[c];
        y = fmaf(sw[c*3+1], hC*mC, y);
        if (hasL) y = fmaf(sw[c*3+0], hL*mL, y);
        if (hasR) y = fmaf(sw[c*3+2], hR*mR, y);
        v[k] = y; s1 += y;
    }
    #pragma unroll
    for (int o=16;o;o>>=1) s1 += __shfl_xor_sync(0xffffffffu, s1, o);
    float mean = s1*(1.f/192.f);
    float s2 = 0.f;
    #pragma unroll
    for (int k=0;k<6;k++){ float e = v[k]-mean; s2 += e*e; }
    #pragma unroll
    for (int o=16;o;o>>=1) s2 += __shfl_xor_sync(0xffffffffu, s2, o);
    float inv = rsqrtf(s2*(1.f/192.f) + 1e-5f);
    float* yo = g_y + (size_t)pos*C;
    #pragma unroll
    for (int k=0;k<6;k++){
        int c = lane + 32*k;
        float u = fmaf(g1[c], (v[k]-mean)*inv, b1[c]);
        yo[c] = geluf(u);
    }
}

// ---------------------------------------------------------------------------
// h = h_base + gelu(LN2(W(192x192) @ y + bias))
// Block: 128 thr (4 warps), M_TILE=32 rows, warp owns 8 full rows (LN warp-local)
// float2-native pipeline: LDS.64 operands, ull accumulators -> pure FFMA2,
// no pack/unpack MOVs around the asm.
// first=1: h_base computed inline as pre_w[co]*x0 + pre_b[co]
// ---------------------------------------------------------------------------
__global__ __launch_bounds__(128, 3) void pw_ln_gelu_res_kernel(
    const float* __restrict__ W, const float* __restrict__ bias,
    const float* __restrict__ g2, const float* __restrict__ b2,
    const float* __restrict__ x,  const float* __restrict__ prew,
    const float* __restrict__ preb, int first)
{
    __shared__ float2 Ws2[16*193];   // [ci2][co], stride 193 float2
    __shared__ float2 ys2[32*17];    // [m][ci2],  stride 17 float2
    __shared__ float  x0s[32];
    int tid = threadIdx.x;
    int lane = tid & 31, w = tid >> 5;
    size_t m0 = (size_t)blockIdx.x * 32;

    if (first && tid < 32) {
        size_t pos = m0 + tid;
        x0s[tid] = x[(pos >> 12)*2*TLEN + (pos & 4095u)];
    }

    unsigned long long acc[8][6];
    #pragma unroll
    for (int r=0;r<8;r++)
        #pragma unroll
        for (int j=0;j<6;j++) acc[r][j] = 0ull;

    for (int kb = 0; kb < 192; kb += 32) {
        #pragma unroll
        for (int idx = tid; idx < 192*16; idx += 128) {
            int co = idx >> 4, ci2 = idx & 15;
            Ws2[ci2*193+co] = *reinterpret_cast<const float2*>(W + co*192 + kb + 2*ci2);
        }
        #pragma unroll
        for (int idx = tid; idx < 32*16; idx += 128) {
            int m = idx >> 4, ci2 = idx & 15;
            ys2[m*17+ci2] = *reinterpret_cast<const float2*>(g_y + (m0+m)*192 + kb + 2*ci2);
        }
        __syncthreads();
        #pragma unroll 4
        for (int ci2 = 0; ci2 < 16; ci2++) {
            unsigned long long a8[8];
            #pragma unroll
            for (int r=0;r<8;r++)
                a8[r] = *reinterpret_cast<const unsigned long long*>(&ys2[(w*8+r)*17 + ci2]);
            #pragma unroll
            for (int j=0;j<6;j++){
                unsigned long long bv =
                    *reinterpret_cast<const unsigned long long*>(&Ws2[ci2*193 + lane + 32*j]);
                #pragma unroll
                for (int r=0;r<8;r++)
                    asm("fma.rn.f32x2 %0, %1, %2, %0;"
                        : "+l"(acc[r][j]) : "l"(a8[r]), "l"(bv));
            }
        }
        __syncthreads();
    }

    #pragma unroll
    for (int r=0;r<8;r++){
        float vv[6]; float s1 = 0.f;
        #pragma unroll
        for (int j=0;j<6;j++){
            int co = lane+32*j;
            unsigned long long a = acc[r][j];
            float lo = __uint_as_float((unsigned)(a & 0xffffffffu));
            float hi = __uint_as_float((unsigned)(a >> 32));
            float vx = lo + hi + bias[co];
            vv[j] = vx; s1 += vx;
        }
        #pragma unroll
        for (int o=16;o;o>>=1) s1 += __shfl_xor_sync(0xffffffffu, s1, o);
        float mean = s1*(1.f/192.f);
        float s2 = 0.f;
        #pragma unroll
        for (int j=0;j<6;j++){ float e = vv[j]-mean; s2 += e*e; }
        #pragma unroll
        for (int o=16;o;o>>=1) s2 += __shfl_xor_sync(0xffffffffu, s2, o);
        float inv = rsqrtf(s2*(1.f/192.f) + 1e-5f);
        size_t rowo = (m0 + (size_t)(w*8+r))*C;
        float x0v = first ? x0s[w*8+r] : 0.f;
        #pragma unroll
        for (int j=0;j<6;j++){
            int co = lane+32*j;
            float u = fmaf(g2[co], (vv[j]-mean)*inv, b2[co]);
            float base = first ? fmaf(prew[co], x0v, preb[co]) : g_h[rowo+co];
            g_h[rowo+co] = base + geluf(u);
        }
    }
}

// ---------------------------------------------------------------------------
// p[pos, j] = (mask * sum_ci Wp[j,ci]*h[pos,ci] + bp[j]) * mask, j<29
// ---------------------------------------------------------------------------
__global__ __launch_bounds__(256) void proj_kernel(
    const float* __restrict__ Wp, const float* __restrict__ bp,
    const float* __restrict__ mask)
{
    int warp = threadIdx.x >> 5, lane = threadIdx.x & 31;
    int pos = blockIdx.x*8 + warp;
    float m = mask[pos];
    const float* hrow = g_h + (size_t)pos*C;
    float hv[6];
    #pragma unroll
    for (int k=0;k<6;k++) hv[k] = hrow[lane+32*k];
    float acc[29];
    #pragma unroll
    for (int j=0;j<29;j++) acc[j]=0.f;
    #pragma unroll
    for (int k=0;k<6;k++){
        int c = lane+32*k;
        #pragma unroll
        for (int j=0;j<29;j++)
            acc[j] = fmaf(Wp[j*192+c], hv[k], acc[j]);
    }
    #pragma unroll
    for (int o=16;o;o>>=1){
        #pragma unroll
        for (int j=0;j<29;j++) acc[j] += __shfl_xor_sync(0xffffffffu, acc[j], o);
    }
    float sel = 0.f;
    #pragma unroll
    for (int j=0;j<29;j++) if (lane==j) sel = acc[j];
    if (lane < 29)
        g_p[(size_t)pos*32 + lane] = fmaf(m, sel, bp[lane]) * m;
}

// ---------------------------------------------------------------------------
// rational-quadratic spline, writes both output halves + per-position lad
// ---------------------------------------------------------------------------
__global__ __launch_bounds__(256) void spline_kernel(
    const float* __restrict__ x, const float* __restrict__ mask,
    float* __restrict__ out)
{
    int pos = blockIdx.x*256 + threadIdx.x;
    int b = pos >> 12, t = pos & 4095;
    float m = mask[pos];
    const float* p = g_p + (size_t)pos*32;
    const float SCALE = 13.856406460551018f; // sqrt(192)

    float x0v = x[(size_t)b*2*TLEN + t];
    float x1v = x[(size_t)b*2*TLEN + TLEN + t];

    float cw[11], wd[10];
    {
        float u[10]; float mx = -1e30f;
        #pragma unroll
        for (int k=0;k<10;k++){ u[k] = p[k]/SCALE; mx = fmaxf(mx,u[k]); }
        float s=0.f; float e[10];
        #pragma unroll
        for (int k=0;k<10;k++){ e[k]=expf(u[k]-mx); s+=e[k]; }
        float run=0.f; cw[0]=-5.f;
        #pragma unroll
        for (int k=0;k<10;k++){ run += 0.001f + 0.99f*(e[k]/s); cw[k+1] = 10.f*run - 5.f; }
        cw[10] = 5.f;
        #pragma unroll
        for (int k=0;k<10;k++) wd[k] = cw[k+1]-cw[k];
    }
    float ch[11], hg[10];
    {
        float u[10]; float mx = -1e30f;
        #pragma unroll
        for (int k=0;k<10;k++){ u[k] = p[10+k]/SCALE; mx = fmaxf(mx,u[k]); }
        float s=0.f; float e[10];
        #pragma unroll
        for (int k=0;k<10;k++){ e[k]=expf(u[k]-mx); s+=e[k]; }
        float run=0.f; ch[0]=-5.f;
        #pragma unroll
        for (int k=0;k<10;k++){ run += 0.001f + 0.99f*(e[k]/s); ch[k+1] = 10.f*run - 5.f; }
        ch[10] = 5.f;
        #pragma unroll
        for (int k=0;k<10;k++) hg[k] = ch[k+1]-ch[k];
    }
    float dv[11];
    dv[0] = 1.0f; dv[10] = 1.0f;   // 0.001 + softplus(log(exp(0.999)-1)) = 1.0
    #pragma unroll
    for (int k=0;k<9;k++){
        float q = p[20+k];
        float sp = (q > 20.f) ? q : log1pf(expf(q));
        dv[k+1] = 0.001f + sp;
    }
    float xin = fminf(fmaxf(x1v, -5.f), 5.f);
    int cnt = 0;
    #pragma unroll
    for (int k=0;k<10;k++) cnt += (xin >= cw[k]) ? 1 : 0;
    int bin = cnt-1; if (bin < 0) bin = 0; if (bin > 9) bin = 9;

    float icw=cw[bin], iw=wd[bin], ich=ch[bin], ih=hg[bin];
    float dl=dv[bin], dr=dv[bin+1];
    float delta = ih/iw;
    float th  = (xin - icw)/iw;
    float t1m = th*(1.f-th);
    float num = ih*(delta*th*th + dl*t1m);
    float den = delta + (dl+dr-2.f*delta)*t1m;
    float yv  = ich + num/den;
    float onem = 1.f-th;
    float dnum = delta*delta*(dr*th*th + 2.f*delta*t1m + dl*onem*onem);
    float lad  = logf(dnum) - 2.f*logf(den);
    bool inside = (x1v >= -5.f) && (x1v <= 5.f);
    float xo   = inside ? yv  : x1v;
    float ladv = inside ? lad : 0.f;

    out[(size_t)b*2*TLEN + t]        = x0v * m;
    out[(size_t)b*2*TLEN + TLEN + t] = xo  * m;
    g_lad[pos] = ladv * m;
}

// ---------------------------------------------------------------------------
// deterministic per-batch logdet reduction (fixed order, no atomics)
// ---------------------------------------------------------------------------
__global__ void logdet_kernel(float* __restrict__ out) {
    int b = blockIdx.x, tid = threadIdx.x;
    float s = 0.f;
    #pragma unroll
    for (int k=0;k<16;k++) s += g_lad[b*TLEN + k*256 + tid];
    __shared__ float sm[256];
    sm[tid] = s; __syncthreads();
    #pragma unroll
    for (int o=128;o;o>>=1){ if (tid<o) sm[tid]+=sm[tid+o]; __syncthreads(); }
    if (tid==0) out[b] = sm[0];
}

extern "C" void kernel_launch(void* const* d_in, const int* in_sizes, int n_in,
                              void* d_out, int out_size) {
    const float* x      = (const float*)d_in[0];
    const float* mask   = (const float*)d_in[1];
    const float* pre_w  = (const float*)d_in[2];
    const float* pre_b  = (const float*)d_in[3];
    const float* sep_w  = (const float*)d_in[4];
    const float* sep_b  = (const float*)d_in[5];
    const float* pw_w   = (const float*)d_in[6];
    const float* pw_b   = (const float*)d_in[7];
    const float* ln1_g  = (const float*)d_in[8];
    const float* ln1_b  = (const float*)d_in[9];
    const float* ln2_g  = (const float*)d_in[10];
    const float* ln2_b  = (const float*)d_in[11];
    const float* proj_w = (const float*)d_in[12];
    const float* proj_b = (const float*)d_in[13];
    float* out = (float*)d_out;

    int d = 1;
    for (int i = 0; i < 3; i++) {
        int first = (i == 0);
        dw_ln_gelu_kernel<<<BT/8, 256>>>(sep_w + (size_t)i*C*3, sep_b + (size_t)i*C,
                                         ln1_g + (size_t)i*C, ln1_b + (size_t)i*C,
                                         mask, d, x, pre_w, pre_b, first);
        pw_ln_gelu_res_kernel<<<BT/32, 128>>>(pw_w + (size_t)i*C*C, pw_b + (size_t)i*C,
                                              ln2_g + (size_t)i*C, ln2_b + (size_t)i*C,
                                              x, pre_w, pre_b, first);
        d *= 3;
    }

    proj_kernel<<<BT/8, 256>>>(proj_w, proj_b, mask);
    spline_kernel<<<BT/256, 256>>>(x, mask, out);
    logdet_kernel<<<64, 256>>>(out + (size_t)BATCH*2*TLEN);
}